// round 5
// baseline (speedup 1.0000x reference)
#include <cuda_runtime.h>
#include <cuda_bf16.h>
#include <cstdint>

// Problem constants (fixed by the dataset):
//   e_src: (16, 1024, 8, 256) fp32
//   d_src: (16, 128) int32  (jax randint silently downgrades int64->int32)
//   output: (8, 128, 256) fp32
#define BH 8
#define TT 1024
#define FF 8
#define SS 128
#define CC 256
#define ROWB 1024                     // bytes per (t,f) row = 256 fp32
#define C4 64                         // float4 per row
#define CHUNK_ROWS 16
#define CHUNK_BYTES (CHUNK_ROWS * ROWB)   // 16 KB
#define DEPTH 4
#define NCONS 256                     // consumer threads (warps 0-7)
#define NTHREADS 288                  // + warp 8 = producer

// Dynamic smem layout (bytes):
#define OFF_STAGE 0
#define OFF_RED   (DEPTH * CHUNK_BYTES)          // 65536: float4 red[256]
#define OFF_SD    (OFF_RED + NCONS * 16)         // 69632: int sd[128]
#define OFF_WSUM  (OFF_SD + SS * 4)              // 70144: int wsum[4]
#define OFF_BAR   (OFF_WSUM + 64)                // 70208: u64 full[4], empty[4]
#define SMEM_TOTAL (OFF_BAR + 8 * 8 + 64)

__device__ __forceinline__ uint32_t smem_u32(const void* p) {
    uint32_t a;
    asm("{ .reg .u64 t; cvta.to.shared.u64 t, %1; cvt.u32.u64 %0, t; }"
        : "=r"(a) : "l"(p));
    return a;
}
__device__ __forceinline__ void mbar_init(uint32_t mbar, uint32_t cnt) {
    asm volatile("mbarrier.init.shared.b64 [%0], %1;" :: "r"(mbar), "r"(cnt) : "memory");
}
__device__ __forceinline__ void mbar_expect_tx(uint32_t mbar, uint32_t bytes) {
    asm volatile("mbarrier.arrive.expect_tx.shared.b64 _, [%0], %1;"
                 :: "r"(mbar), "r"(bytes) : "memory");
}
__device__ __forceinline__ void mbar_arrive(uint32_t mbar) {
    asm volatile("mbarrier.arrive.shared.b64 _, [%0];" :: "r"(mbar) : "memory");
}
__device__ __forceinline__ void mbar_wait(uint32_t mbar, uint32_t parity) {
    uint32_t done;
    asm volatile(
        "{\n\t.reg .pred p;\n\t"
        "mbarrier.try_wait.parity.acquire.cta.shared::cta.b64 p, [%1], %2;\n\t"
        "selp.b32 %0, 1, 0, p;\n\t}"
        : "=r"(done) : "r"(mbar), "r"(parity) : "memory");
    if (!done) {
        asm volatile(
            "{\n\t.reg .pred P1;\n\t"
            "W_%=:\n\t"
            "mbarrier.try_wait.parity.acquire.cta.shared::cta.b64 P1, [%0], %1, 0x989680;\n\t"
            "@P1 bra.uni D_%=;\n\t"
            "bra.uni W_%=;\n\t"
            "D_%=:\n\t}"
            :: "r"(mbar), "r"(parity) : "memory");
    }
}
__device__ __forceinline__ void bulk_g2s(uint32_t dst_smem, const void* src,
                                         uint32_t bytes, uint32_t mbar) {
    asm volatile(
        "cp.async.bulk.shared::cta.global.mbarrier::complete_tx::bytes "
        "[%0], [%1], %2, [%3];"
        :: "r"(dst_smem), "l"(src), "r"(bytes), "r"(mbar) : "memory");
}

// One block per (b, s). Warp 8 = TMA producer (4-stage, 16KB chunks);
// warps 0-7 = consumers reducing from smem. Each consumer thread owns
// float4-channel c4 = tid & 63 and rows g, g+4, g+8, g+12 within a chunk.
__global__ void __launch_bounds__(NTHREADS, 1)
agg_tma_kernel(const float* __restrict__ e,
               const int* __restrict__ dsrc,
               float* __restrict__ out) {
    extern __shared__ char smem[];
    const uint32_t sbase = smem_u32(smem);
    const int s = blockIdx.x;
    const int b = blockIdx.y;
    const int tid = threadIdx.x;

    int* sd   = (int*)(smem + OFF_SD);
    int* wsum = (int*)(smem + OFF_WSUM);
    float4* red = (float4*)(smem + OFF_RED);
    const uint32_t full_bar  = sbase + OFF_BAR;         // full[st]  = +8*st
    const uint32_t empty_bar = sbase + OFF_BAR + 32;    // empty[st] = +8*st

    // --- init barriers + load durations ---
    if (tid == 0) {
        #pragma unroll
        for (int st = 0; st < DEPTH; st++) {
            mbar_init(full_bar + 8 * st, 1);
            mbar_init(empty_bar + 8 * st, NCONS);
        }
    }
    if (tid < SS) sd[tid] = dsrc[b * SS + tid];
    __syncthreads();

    // off = sum_{i<s} d[i] : warps 0-3 reduce (threads 0..127)
    if (tid < SS) {
        int part = (tid < s) ? sd[tid] : 0;
        #pragma unroll
        for (int o = 16; o > 0; o >>= 1)
            part += __shfl_down_sync(0xffffffffu, part, o);
        if ((tid & 31) == 0) wsum[tid >> 5] = part;
    }
    __syncthreads();

    const int off = wsum[0] + wsum[1] + wsum[2] + wsum[3];
    const int dv  = sd[s];
    const int start = min(off, TT);
    const int end   = min(off + dv, TT);
    const int nrows = (end - start) * FF;            // <= 120
    const uint32_t nbytes = (uint32_t)nrows * ROWB;  // <= 122880
    const int nck = (int)((nbytes + CHUNK_BYTES - 1) / CHUNK_BYTES);  // <= 8

    const char* src = (const char*)e +
        ((size_t)b * TT * FF + (size_t)start * FF) * ROWB;

    if (tid >= NCONS) {
        // ---- producer (warp 8, lane 0) ----
        if (tid == NCONS) {
            for (int k = 0; k < nck; k++) {
                const int st = k & (DEPTH - 1);
                const uint32_t par = 1u ^ ((k >> 2) & 1u);   // empty parity
                mbar_wait(empty_bar + 8 * st, par);
                const uint32_t bytes =
                    min((uint32_t)CHUNK_BYTES, nbytes - (uint32_t)k * CHUNK_BYTES);
                mbar_expect_tx(full_bar + 8 * st, bytes);
                bulk_g2s(sbase + OFF_STAGE + st * CHUNK_BYTES,
                         src + (size_t)k * CHUNK_BYTES, bytes,
                         full_bar + 8 * st);
            }
        }
    } else {
        // ---- consumers (warps 0-7) ----
        const int c4 = tid & 63;
        const int g  = tid >> 6;        // 0..3
        float4 acc = make_float4(0.f, 0.f, 0.f, 0.f);
        for (int k = 0; k < nck; k++) {
            const int st = k & (DEPTH - 1);
            const uint32_t par = (uint32_t)((k >> 2) & 1);   // full parity
            mbar_wait(full_bar + 8 * st, par);
            const int rows = min(CHUNK_ROWS, nrows - k * CHUNK_ROWS);
            const float4* stage =
                (const float4*)(smem + OFF_STAGE + st * CHUNK_BYTES);
            #pragma unroll
            for (int r = g; r < CHUNK_ROWS; r += 4) {
                if (r < rows) {
                    float4 v = stage[r * C4 + c4];
                    acc.x += v.x; acc.y += v.y; acc.z += v.z; acc.w += v.w;
                }
            }
            mbar_arrive(empty_bar + 8 * st);
        }
        red[tid] = acc;
    }
    __syncthreads();

    // ---- final 4-way reduce + scale + store (threads 0..63) ----
    if (tid < 64) {
        float4 r = red[tid];
        #pragma unroll
        for (int w = 1; w < 4; w++) {
            float4 a = red[w * 64 + tid];
            r.x += a.x; r.y += a.y; r.z += a.z; r.w += a.w;
        }
        const float inv = (dv > 0) ? (1.0f / (float)(dv * FF)) : 0.0f;
        r.x *= inv; r.y *= inv; r.z *= inv; r.w *= inv;
        ((float4*)out)[((size_t)b * SS + s) * C4 + tid] = r;
    }
}

extern "C" void kernel_launch(void* const* d_in, const int* in_sizes, int n_in,
                              void* d_out, int out_size) {
    // e_src is the large tensor (33,554,432 elems); d_src is 2048 elems.
    int ei = 0, di = 1;
    if (n_in >= 2 && in_sizes[0] < in_sizes[1]) { ei = 1; di = 0; }

    const float* e = (const float*)d_in[ei];   // (16,1024,8,256) fp32
    const int*   d = (const int*)d_in[di];     // (16,128) int32
    float* out = (float*)d_out;                // (8,128,256) fp32

    cudaFuncSetAttribute(agg_tma_kernel,
                         cudaFuncAttributeMaxDynamicSharedMemorySize, SMEM_TOTAL);
    dim3 grid(SS, BH);
    agg_tma_kernel<<<grid, NTHREADS, SMEM_TOTAL>>>(e, d, out);
}